// round 2
// baseline (speedup 1.0000x reference)
#include <cuda_runtime.h>
#include <cstdint>

#define T_STEPS 512
#define BATCH   512
#define FEAT    128
#define HID     512
#define TAGS    2
#define NG      2048          // 4*HID
#define K1      640           // FEAT + HID
#define K2      1024          // HID + HID
#define NCTA    128
#define MT      64
#define NT      128
#define NTHREADS 128

// dynamic smem (floats): A bufs 2*64*36, B bufs 2*128*36
#define SMEM_FLOATS (2*64*36 + 2*128*36)   // 13824
#define SMEM_BYTES  (SMEM_FLOATS*4)        // 55296

// ------------------------- device globals (scratch) -------------------------
__device__ float g_Wp1[NG * K1];         // permuted [n][k], tf32-rounded
__device__ float g_Wp2[NG * K2];
__device__ float g_b1[NG];
__device__ float g_b2[NG];
__device__ float g_h1[2][BATCH * HID];
__device__ float g_h2[2][BATCH * HID];
__device__ float g_c1[BATCH * HID];
__device__ float g_c2[BATCH * HID];
__device__ unsigned g_bar;
__device__ unsigned g_gen;

// ------------------------------- helpers ------------------------------------
__device__ __forceinline__ float to_tf32(float x) {
    unsigned u; asm("cvt.rna.tf32.f32 %0, %1;" : "=r"(u) : "f"(x));
    return __uint_as_float(u);
}
__device__ __forceinline__ float sigm(float x) {
    return 1.0f / (1.0f + __expf(-x));
}
__device__ __forceinline__ void cp16(uint32_t dst, const float* src) {
    asm volatile("cp.async.cg.shared.global [%0], [%1], 16;\n" :: "r"(dst), "l"(src));
}

// permuted column index n -> original gate row:
//   chunk = n>>7 (16 h-chunks), w = n&127, q = w>>5 (gate), r = w&31
//   orig = q*HID + chunk*32 + r
__device__ __forceinline__ int orig_row(long n) {
    int chunk = (int)(n >> 7), w = (int)(n & 127);
    int q = w >> 5, r = w & 31;
    return q * HID + chunk * 32 + r;
}

// ------------------------------ prep kernel ---------------------------------
__global__ void prep_kernel(const float* __restrict__ Wih1, const float* __restrict__ Whh1,
                            const float* __restrict__ bih1, const float* __restrict__ bhh1,
                            const float* __restrict__ Wih2, const float* __restrict__ Whh2,
                            const float* __restrict__ bih2, const float* __restrict__ bhh2) {
    const long NW1 = (long)NG * K1;
    const long NW2 = (long)NG * K2;
    const long NSTATE = 4L * BATCH * HID;
    const long TOT = NW1 + NW2 + 2L * NG + NSTATE;
    for (long i = blockIdx.x * (long)blockDim.x + threadIdx.x; i < TOT;
         i += (long)gridDim.x * blockDim.x) {
        if (i < NW1) {
            long n = i / K1, k = i % K1;
            int o = orig_row(n);
            float v = (k < FEAT) ? Wih1[(long)o * FEAT + k]
                                 : Whh1[(long)o * HID + (k - FEAT)];
            g_Wp1[i] = to_tf32(v);
        } else if (i < NW1 + NW2) {
            long j = i - NW1;
            long n = j / K2, k = j % K2;
            int o = orig_row(n);
            float v = (k < HID) ? Wih2[(long)o * HID + k]
                                : Whh2[(long)o * HID + (k - HID)];
            g_Wp2[j] = to_tf32(v);
        } else if (i < NW1 + NW2 + NG) {
            long n = i - NW1 - NW2;
            int o = orig_row(n);
            g_b1[n] = bih1[o] + bhh1[o];
        } else if (i < NW1 + NW2 + 2L * NG) {
            long n = i - NW1 - NW2 - NG;
            int o = orig_row(n);
            g_b2[n] = bih2[o] + bhh2[o];
        } else {
            long j = i - (NW1 + NW2 + 2L * NG);
            long seg = j / (BATCH * HID), o = j % (BATCH * HID);
            if      (seg == 0) g_h1[0][o] = 0.f;
            else if (seg == 1) g_h2[0][o] = 0.f;
            else if (seg == 2) g_c1[o]    = 0.f;
            else               g_c2[o]    = 0.f;
        }
    }
    if (blockIdx.x == 0 && threadIdx.x == 0) { g_bar = 0u; g_gen = 0u; }
}

// ------------------------------ grid barrier --------------------------------
__device__ __forceinline__ void grid_sync(unsigned target) {
    __syncthreads();
    if (threadIdx.x == 0) {
        __threadfence();
        unsigned a = atomicAdd(&g_bar, 1u);
        if (a == NCTA - 1u) {
            atomicExch(&g_bar, 0u);
            __threadfence();
            atomicAdd(&g_gen, 1u);
        } else {
            while (atomicAdd(&g_gen, 0u) < target) { }
        }
        __threadfence();
    }
    __syncthreads();
}

// --------------------------------- GEMM -------------------------------------
struct GArgs {
    const float* a0; int lda0; int split;   // chunks < split come from a0
    const float* a1; int lda1;              // remaining chunks from a1
    const float* B;  int ldb;  int nch;     // B: [n][k] permuted weights
};

__device__ __forceinline__ void gemm_tile(const GArgs g, float acc[2][8][4],
                                          float* sm, uint32_t smu) {
    const int tid  = threadIdx.x;
    const int lane = tid & 31, wid = tid >> 5;
    const int wy = wid >> 1, wx = wid & 1;

    auto issue = [&](int ck) {
        const int p = ck & 1;
        {   // A tile: 64 rows x 32 floats; 128 threads -> 4 x 16B each
            int row = tid & 63;
            int jb  = (tid >> 6) * 4;
            const float* src = (ck < g.split)
                ? g.a0 + (size_t)row * g.lda0 + ck * 32 + jb * 4
                : g.a1 + (size_t)row * g.lda1 + (ck - g.split) * 32 + jb * 4;
            uint32_t dst = smu + (uint32_t)(p * 2304 + row * 36 + jb * 4) * 4u;
            #pragma unroll
            for (int j = 0; j < 4; j++) cp16(dst + j * 16, src + j * 4);
        }
        {   // B tile: 128 rows x 32 floats; 1 row/thread, 8 x 16B
            int row = tid;
            const float* src = g.B + (size_t)row * g.ldb + ck * 32;
            uint32_t dst = smu + (uint32_t)(4608 + p * 4608 + row * 36) * 4u;
            #pragma unroll
            for (int j = 0; j < 8; j++) cp16(dst + j * 16, src + j * 4);
        }
        asm volatile("cp.async.commit_group;\n");
    };

    issue(0);
    for (int ck = 0; ck < g.nch; ck++) {
        if (ck + 1 < g.nch) { issue(ck + 1); asm volatile("cp.async.wait_group 1;\n"); }
        else                {                asm volatile("cp.async.wait_group 0;\n"); }
        __syncthreads();
        const float* sA = sm + (ck & 1) * 2304;
        const float* sB = sm + 4608 + (ck & 1) * 4608;
        #pragma unroll
        for (int k8 = 0; k8 < 4; k8++) {
            const int kk = k8 * 8 + (lane & 3);
            unsigned a[2][4];
            #pragma unroll
            for (int mi = 0; mi < 2; mi++) {
                int row = wy * 32 + mi * 16 + (lane >> 2);
                a[mi][0] = __float_as_uint(sA[row * 36 + kk]);
                a[mi][1] = __float_as_uint(sA[(row + 8) * 36 + kk]);
                a[mi][2] = __float_as_uint(sA[row * 36 + kk + 4]);
                a[mi][3] = __float_as_uint(sA[(row + 8) * 36 + kk + 4]);
            }
            #pragma unroll
            for (int ni = 0; ni < 8; ni++) {
                int col = wx * 64 + ni * 8 + (lane >> 2);
                unsigned b0 = __float_as_uint(sB[col * 36 + kk]);
                unsigned b1 = __float_as_uint(sB[col * 36 + kk + 4]);
                #pragma unroll
                for (int mi = 0; mi < 2; mi++) {
                    asm volatile(
                        "mma.sync.aligned.m16n8k8.row.col.f32.tf32.tf32.f32 "
                        "{%0,%1,%2,%3}, {%4,%5,%6,%7}, {%8,%9}, {%0,%1,%2,%3};\n"
                        : "+f"(acc[mi][ni][0]), "+f"(acc[mi][ni][1]),
                          "+f"(acc[mi][ni][2]), "+f"(acc[mi][ni][3])
                        : "r"(a[mi][0]), "r"(a[mi][1]), "r"(a[mi][2]), "r"(a[mi][3]),
                          "r"(b0), "r"(b1));
                }
            }
        }
        __syncthreads();
    }
}

// ------------------------------ LSTM epilogue -------------------------------
__device__ __forceinline__ void lstm_epilogue(float acc[2][8][4], float* sm,
                                              const float* __restrict__ bias, int n0,
                                              float* __restrict__ cbuf,
                                              float* __restrict__ hout,
                                              int m0, int H0) {
    const int tid = threadIdx.x, lane = tid & 31, wid = tid >> 5;
    const int wy = wid >> 1, wx = wid & 1;
    // scatter accumulators to smem gate buffer, stride 132
    #pragma unroll
    for (int mi = 0; mi < 2; mi++) {
        #pragma unroll
        for (int ni = 0; ni < 8; ni++) {
            int row = wy * 32 + mi * 16 + (lane >> 2);
            int col = wx * 64 + ni * 8 + 2 * (lane & 3);
            sm[row * 132 + col]           = acc[mi][ni][0];
            sm[row * 132 + col + 1]       = acc[mi][ni][1];
            sm[(row + 8) * 132 + col]     = acc[mi][ni][2];
            sm[(row + 8) * 132 + col + 1] = acc[mi][ni][3];
        }
    }
    __syncthreads();
    #pragma unroll
    for (int it = 0; it < (MT * 32) / NTHREADS; it++) {
        int p  = it * NTHREADS + tid;
        int bl = p >> 5, r = p & 31;
        float gi = sm[bl * 132 + r]       + bias[n0 + r];
        float gf = sm[bl * 132 + 32 + r]  + bias[n0 + 32 + r];
        float gg = sm[bl * 132 + 64 + r]  + bias[n0 + 64 + r];
        float go = sm[bl * 132 + 96 + r]  + bias[n0 + 96 + r];
        int gidx = (m0 + bl) * HID + H0 + r;
        float c  = cbuf[gidx];
        float cn = sigm(gf) * c + sigm(gi) * tanhf(gg);
        cbuf[gidx] = cn;
        hout[gidx] = sigm(go) * tanhf(cn);
    }
}

// ----------------------------- output projection ----------------------------
__device__ __forceinline__ void out_calc(int tp, const float* __restrict__ h2cur,
                                         const float* __restrict__ Wlin,
                                         const float* __restrict__ blin,
                                         float* __restrict__ out, int ct) {
    const int lane = threadIdx.x & 31, wid = threadIdx.x >> 5;
    const int b = ct * 4 + wid;                     // 128 CTAs x 4 rows = 512
    const float* hrow = h2cur + (size_t)b * HID;
    float s0 = 0.f, s1 = 0.f;
    #pragma unroll
    for (int k = lane; k < HID; k += 32) {
        float hv = __ldcg(hrow + k);                // bypass L1 (cross-CTA writer)
        s0 += hv * __ldg(Wlin + k);
        s1 += hv * __ldg(Wlin + HID + k);
    }
    #pragma unroll
    for (int o = 16; o; o >>= 1) {
        s0 += __shfl_xor_sync(0xffffffffu, s0, o);
        s1 += __shfl_xor_sync(0xffffffffu, s1, o);
    }
    if (lane == 0) {
        out[(size_t)b * (T_STEPS * TAGS) + tp * TAGS + 0] = s0 + blin[0];
        out[(size_t)b * (T_STEPS * TAGS) + tp * TAGS + 1] = s1 + blin[1];
    }
}

// ------------------------------ persistent kernel ---------------------------
__global__ void __launch_bounds__(NTHREADS, 1)
lstm_persistent(const float* __restrict__ signal, const float* __restrict__ Wlin,
                const float* __restrict__ blin, float* __restrict__ out) {
    extern __shared__ float sm[];
    const uint32_t smu = (uint32_t)__cvta_generic_to_shared(sm);
    const int ct = blockIdx.x;
    const int mt = ct >> 4, nt = ct & 15;
    const int m0 = mt * MT, n0 = nt * NT, H0 = nt * 32;
    unsigned round = 0;
    float acc[2][8][4];

    for (int t = 0; t < T_STEPS; t++) {
        const int rb = t & 1, wb = rb ^ 1;
        if (t > 0) out_calc(t - 1, g_h2[rb], Wlin, blin, out, ct);

        // ---- phase A: gates1 = [x_t, h1] @ W1p^T ----
        #pragma unroll
        for (int mi = 0; mi < 2; mi++)
            #pragma unroll
            for (int ni = 0; ni < 8; ni++)
                #pragma unroll
                for (int r4 = 0; r4 < 4; r4++) acc[mi][ni][r4] = 0.f;
        {
            GArgs ga;
            ga.a0 = signal + ((size_t)t * BATCH + m0) * FEAT; ga.lda0 = FEAT; ga.split = FEAT / 32;
            ga.a1 = g_h1[rb] + (size_t)m0 * HID;              ga.lda1 = HID;
            ga.B  = g_Wp1 + (size_t)n0 * K1;                  ga.ldb  = K1;  ga.nch = K1 / 32;
            gemm_tile(ga, acc, sm, smu);
        }
        lstm_epilogue(acc, sm, g_b1, n0, g_c1, g_h1[wb], m0, H0);
        grid_sync(++round);

        // ---- phase B: gates2 = [h1', h2] @ W2p^T ----
        #pragma unroll
        for (int mi = 0; mi < 2; mi++)
            #pragma unroll
            for (int ni = 0; ni < 8; ni++)
                #pragma unroll
                for (int r4 = 0; r4 < 4; r4++) acc[mi][ni][r4] = 0.f;
        {
            GArgs gb;
            gb.a0 = g_h1[wb] + (size_t)m0 * HID; gb.lda0 = HID; gb.split = HID / 32;
            gb.a1 = g_h2[rb] + (size_t)m0 * HID; gb.lda1 = HID;
            gb.B  = g_Wp2 + (size_t)n0 * K2;     gb.ldb  = K2;  gb.nch = K2 / 32;
            gemm_tile(gb, acc, sm, smu);
        }
        lstm_epilogue(acc, sm, g_b2, n0, g_c2, g_h2[wb], m0, H0);
        grid_sync(++round);
    }
    out_calc(T_STEPS - 1, g_h2[T_STEPS & 1], Wlin, blin, out, ct);
}

// --------------------------------- launcher ---------------------------------
extern "C" void kernel_launch(void* const* d_in, const int* in_sizes, int n_in,
                              void* d_out, int out_size) {
    const float* signal = (const float*)d_in[0];
    const float* Wih1   = (const float*)d_in[1];
    const float* Whh1   = (const float*)d_in[2];
    const float* bih1   = (const float*)d_in[3];
    const float* bhh1   = (const float*)d_in[4];
    const float* Wih2   = (const float*)d_in[5];
    const float* Whh2   = (const float*)d_in[6];
    const float* bih2   = (const float*)d_in[7];
    const float* bhh2   = (const float*)d_in[8];
    const float* Wlin   = (const float*)d_in[9];
    const float* blin   = (const float*)d_in[10];
    float* out = (float*)d_out;

    (void)in_sizes; (void)n_in; (void)out_size;

    cudaFuncSetAttribute(lstm_persistent,
                         cudaFuncAttributeMaxDynamicSharedMemorySize, SMEM_BYTES);

    prep_kernel<<<4096, 256>>>(Wih1, Whh1, bih1, bhh1, Wih2, Whh2, bih2, bhh2);
    lstm_persistent<<<NCTA, NTHREADS, SMEM_BYTES>>>(signal, Wlin, blin, out);
}

// round 4
// speedup vs baseline: 1.0683x; 1.0683x over previous
#include <cuda_runtime.h>
#include <cstdint>

#define T_STEPS 512
#define BATCH   512
#define FEAT    128
#define HID     512
#define TAGS    2
#define NG      2048          // 4*HID
#define K1      640           // FEAT + HID
#define K2      1024          // HID + HID
#define NCTA    128
#define MT      64
#define NT      128
#define NTHREADS 256          // 8 warps: 2 K-groups x 4 warps
#define STAGES  4

// stage layout (bytes): A 64x36 floats = 9216, B 128x36 floats = 18432
#define STAGE_BYTES 27648
#define GROUP_BYTES (STAGES * STAGE_BYTES)       // 110592
#define SMEM_BYTES  (2 * GROUP_BYTES)            // 221184

// ------------------------- device globals (scratch) -------------------------
__device__ float g_Wp1[NG * K1];         // permuted [n][k], tf32-rounded
__device__ float g_Wp2[NG * K2];
__device__ float g_b1[NG];
__device__ float g_b2[NG];
__device__ float g_h1[2][BATCH * HID];
__device__ float g_h2[2][BATCH * HID];
__device__ float g_c1[BATCH * HID];
__device__ float g_c2[BATCH * HID];
__device__ unsigned g_bar;
__device__ unsigned g_gen;

// ------------------------------- helpers ------------------------------------
__device__ __forceinline__ float to_tf32(float x) {
    unsigned u; asm("cvt.rna.tf32.f32 %0, %1;" : "=r"(u) : "f"(x));
    return __uint_as_float(u);
}
__device__ __forceinline__ float sigm(float x) { return 1.0f / (1.0f + __expf(-x)); }
__device__ __forceinline__ void cp16(uint32_t dst, const float* src) {
    asm volatile("cp.async.cg.shared.global [%0], [%1], 16;\n" :: "r"(dst), "l"(src));
}
#define CPA_COMMIT() asm volatile("cp.async.commit_group;\n")
#define CPA_WAIT3()  asm volatile("cp.async.wait_group 3;\n")
#define GBAR(id)     asm volatile("bar.sync %0, %1;" :: "r"(id), "r"(128) : "memory")

// permuted column index n -> original gate row
__device__ __forceinline__ int orig_row(long n) {
    int chunk = (int)(n >> 7), w = (int)(n & 127);
    int q = w >> 5, r = w & 31;
    return q * HID + chunk * 32 + r;
}

// ------------------------------ prep kernel ---------------------------------
__global__ void prep_kernel(const float* __restrict__ Wih1, const float* __restrict__ Whh1,
                            const float* __restrict__ bih1, const float* __restrict__ bhh1,
                            const float* __restrict__ Wih2, const float* __restrict__ Whh2,
                            const float* __restrict__ bih2, const float* __restrict__ bhh2) {
    const long NW1 = (long)NG * K1;
    const long NW2 = (long)NG * K2;
    const long NSTATE = 4L * BATCH * HID;
    const long TOT = NW1 + NW2 + 2L * NG + NSTATE;
    for (long i = blockIdx.x * (long)blockDim.x + threadIdx.x; i < TOT;
         i += (long)gridDim.x * blockDim.x) {
        if (i < NW1) {
            long n = i / K1, k = i % K1;
            int o = orig_row(n);
            float v = (k < FEAT) ? Wih1[(long)o * FEAT + k]
                                 : Whh1[(long)o * HID + (k - FEAT)];
            g_Wp1[i] = to_tf32(v);
        } else if (i < NW1 + NW2) {
            long j = i - NW1;
            long n = j / K2, k = j % K2;
            int o = orig_row(n);
            float v = (k < HID) ? Wih2[(long)o * HID + k]
                                : Whh2[(long)o * HID + (k - HID)];
            g_Wp2[j] = to_tf32(v);
        } else if (i < NW1 + NW2 + NG) {
            long n = i - NW1 - NW2;
            int o = orig_row(n);
            g_b1[n] = bih1[o] + bhh1[o];
        } else if (i < NW1 + NW2 + 2L * NG) {
            long n = i - NW1 - NW2 - NG;
            int o = orig_row(n);
            g_b2[n] = bih2[o] + bhh2[o];
        } else {
            long j = i - (NW1 + NW2 + 2L * NG);
            long seg = j / (BATCH * HID), o = j % (BATCH * HID);
            if      (seg == 0) g_h1[0][o] = 0.f;
            else if (seg == 1) g_h2[0][o] = 0.f;
            else if (seg == 2) g_c1[o]    = 0.f;
            else               g_c2[o]    = 0.f;
        }
    }
    if (blockIdx.x == 0 && threadIdx.x == 0) { g_bar = 0u; g_gen = 0u; }
}

// ------------------------------ grid barrier --------------------------------
__device__ __forceinline__ void grid_sync(unsigned target) {
    __syncthreads();
    if (threadIdx.x == 0) {
        __threadfence();
        unsigned a = atomicAdd(&g_bar, 1u);
        if (a == NCTA - 1u) {
            atomicExch(&g_bar, 0u);
            __threadfence();
            atomicAdd(&g_gen, 1u);
        } else {
            while (atomicAdd(&g_gen, 0u) < target) { }
        }
        __threadfence();
    }
    __syncthreads();
}

// --------------------------------- GEMM -------------------------------------
struct Src {
    const float* a0; int lda0; int split;   // chunks < split from a0
    const float* a1; int lda1;              // remaining from a1
    const float* B;  int ldb;
};

__device__ __forceinline__ void issue_chunk(const Src& s, int ck, uint32_t gbase_u,
                                            int st, int tid_g) {
    // A tile: 64 rows x 32 floats; 2 threads per row, 4 x 16B each
    {
        int row = tid_g & 63;
        int jb  = (tid_g >> 6) * 4;
        const float* src = (ck < s.split)
            ? s.a0 + (size_t)row * s.lda0 + ck * 32 + jb * 4
            : s.a1 + (size_t)row * s.lda1 + (ck - s.split) * 32 + jb * 4;
        uint32_t dst = gbase_u + (uint32_t)(st * STAGE_BYTES) + (uint32_t)(row * 36 + jb * 4) * 4u;
        #pragma unroll
        for (int j = 0; j < 4; j++) cp16(dst + j * 16, src + j * 4);
    }
    // B tile: 128 rows x 32 floats; 1 row per thread, 8 x 16B
    {
        const float* src = s.B + (size_t)tid_g * s.ldb + ck * 32;
        uint32_t dst = gbase_u + (uint32_t)(st * STAGE_BYTES) + 9216u + (uint32_t)tid_g * 144u;
        #pragma unroll
        for (int j = 0; j < 8; j++) cp16(dst + j * 16, src + j * 4);
    }
    CPA_COMMIT();
}

// one K-group runs its half of the chunks through a 4-stage pipeline
__device__ __forceinline__ void run_phase(const Src s, int ckbase, int nch,
                                          const float* gbase_f, uint32_t gbase_u,
                                          int tid_g, int lane, int wy2, int wx2,
                                          int barid, float acc[2][8][4]) {
    #pragma unroll
    for (int mi = 0; mi < 2; mi++)
        #pragma unroll
        for (int ni = 0; ni < 8; ni++)
            #pragma unroll
            for (int r = 0; r < 4; r++) acc[mi][ni][r] = 0.f;

    // prologue: 3 chunks in flight
    #pragma unroll
    for (int p = 0; p < 3; p++) issue_chunk(s, ckbase + p, gbase_u, p, tid_g);

    for (int i = 0; i < nch; i++) {
        if (i + 3 < nch) issue_chunk(s, ckbase + i + 3, gbase_u, (i + 3) & 3, tid_g);
        else             CPA_COMMIT();     // dummy group keeps wait_group count aligned
        CPA_WAIT3();
        GBAR(barid);
        const float* sA = gbase_f + (size_t)(i & 3) * (STAGE_BYTES / 4);
        const float* sB = sA + 2304;
        #pragma unroll
        for (int k8 = 0; k8 < 4; k8++) {
            const int kk = k8 * 8 + (lane & 3);
            unsigned a[2][4];
            #pragma unroll
            for (int mi = 0; mi < 2; mi++) {
                int row = wy2 * 32 + mi * 16 + (lane >> 2);
                a[mi][0] = __float_as_uint(sA[row * 36 + kk]);
                a[mi][1] = __float_as_uint(sA[(row + 8) * 36 + kk]);
                a[mi][2] = __float_as_uint(sA[row * 36 + kk + 4]);
                a[mi][3] = __float_as_uint(sA[(row + 8) * 36 + kk + 4]);
            }
            #pragma unroll
            for (int ni = 0; ni < 8; ni++) {
                int col = wx2 * 64 + ni * 8 + (lane >> 2);
                unsigned b0 = __float_as_uint(sB[col * 36 + kk]);
                unsigned b1 = __float_as_uint(sB[col * 36 + kk + 4]);
                #pragma unroll
                for (int mi = 0; mi < 2; mi++) {
                    asm volatile(
                        "mma.sync.aligned.m16n8k8.row.col.f32.tf32.tf32.f32 "
                        "{%0,%1,%2,%3}, {%4,%5,%6,%7}, {%8,%9}, {%0,%1,%2,%3};\n"
                        : "+f"(acc[mi][ni][0]), "+f"(acc[mi][ni][1]),
                          "+f"(acc[mi][ni][2]), "+f"(acc[mi][ni][3])
                        : "r"(a[mi][0]), "r"(a[mi][1]), "r"(a[mi][2]), "r"(a[mi][3]),
                          "r"(b0), "r"(b1));
                }
            }
        }
        GBAR(barid);   // protect stage from next lap's issue
    }
}

// ------------------------------ LSTM epilogue --------------------------------
// scatter both groups' accumulators into per-group smem buffers, reduce, pointwise
__device__ __forceinline__ void epilogue(float acc[2][8][4], float* smf,
                                         int g, int lane, int wy2, int wx2,
                                         const float* __restrict__ bias, int n0,
                                         float* __restrict__ cbuf,
                                         float* __restrict__ hout,
                                         int m0, int H0) {
    float* buf = smf + (size_t)g * (GROUP_BYTES / 4);
    #pragma unroll
    for (int mi = 0; mi < 2; mi++) {
        #pragma unroll
        for (int ni = 0; ni < 8; ni++) {
            int row = wy2 * 32 + mi * 16 + (lane >> 2);
            int col = wx2 * 64 + ni * 8 + 2 * (lane & 3);
            buf[row * 132 + col]           = acc[mi][ni][0];
            buf[row * 132 + col + 1]       = acc[mi][ni][1];
            buf[(row + 8) * 132 + col]     = acc[mi][ni][2];
            buf[(row + 8) * 132 + col + 1] = acc[mi][ni][3];
        }
    }
    __syncthreads();
    const float* b0 = smf;
    const float* b1 = smf + (GROUP_BYTES / 4);
    const int tid = threadIdx.x;
    #pragma unroll
    for (int it = 0; it < (MT * 32) / NTHREADS; it++) {
        int p  = it * NTHREADS + tid;
        int bl = p >> 5, r = p & 31;
        float gi = b0[bl * 132 + r]      + b1[bl * 132 + r]      + __ldg(bias + n0 + r);
        float gf = b0[bl * 132 + 32 + r] + b1[bl * 132 + 32 + r] + __ldg(bias + n0 + 32 + r);
        float gg = b0[bl * 132 + 64 + r] + b1[bl * 132 + 64 + r] + __ldg(bias + n0 + 64 + r);
        float go = b0[bl * 132 + 96 + r] + b1[bl * 132 + 96 + r] + __ldg(bias + n0 + 96 + r);
        int gidx = (m0 + bl) * HID + H0 + r;
        float c  = cbuf[gidx];
        float cn = sigm(gf) * c + sigm(gi) * tanhf(gg);
        cbuf[gidx] = cn;
        hout[gidx] = sigm(go) * tanhf(cn);
    }
}

// ----------------------------- output projection -----------------------------
__device__ __forceinline__ void out_calc(int tp, const float* __restrict__ h2cur,
                                         const float* __restrict__ Wlin,
                                         const float* __restrict__ blin,
                                         float* __restrict__ out, int ct) {
    const int tid = threadIdx.x, lane = tid & 31, wid = tid >> 5;
    if (wid >= 4) return;
    const int b = ct * 4 + wid;                     // 128 CTAs x 4 rows = 512
    const float* hrow = h2cur + (size_t)b * HID;
    float s0 = 0.f, s1 = 0.f;
    #pragma unroll 8
    for (int k = lane; k < HID; k += 32) {
        float hv = __ldcg(hrow + k);                // bypass L1 (cross-CTA writer)
        s0 += hv * __ldg(Wlin + k);
        s1 += hv * __ldg(Wlin + HID + k);
    }
    #pragma unroll
    for (int o = 16; o; o >>= 1) {
        s0 += __shfl_xor_sync(0xffffffffu, s0, o);
        s1 += __shfl_xor_sync(0xffffffffu, s1, o);
    }
    if (lane == 0) {
        out[(size_t)b * (T_STEPS * TAGS) + tp * TAGS + 0] = s0 + blin[0];
        out[(size_t)b * (T_STEPS * TAGS) + tp * TAGS + 1] = s1 + blin[1];
    }
}

// ------------------------------ persistent kernel ----------------------------
__global__ void __launch_bounds__(NTHREADS, 1)
lstm_persistent(const float* __restrict__ signal, const float* __restrict__ Wlin,
                const float* __restrict__ blin, float* __restrict__ out) {
    extern __shared__ float smf[];
    const uint32_t smu = (uint32_t)__cvta_generic_to_shared(smf);
    const int tid = threadIdx.x;
    const int g = tid >> 7;                 // K-group 0/1
    const int tid_g = tid & 127;
    const int lane = tid & 31;
    const int wig = (tid_g >> 5);           // warp in group 0..3
    const int wy2 = wig >> 1, wx2 = wig & 1;
    const int barid = 1 + g;
    const float* gbase_f = smf + (size_t)g * (GROUP_BYTES / 4);
    const uint32_t gbase_u = smu + (uint32_t)g * GROUP_BYTES;

    const int ct = blockIdx.x;
    const int mt = ct >> 4, nt = ct & 15;   // 8 M-tiles x 16 N-tiles
    const int m0 = mt * MT, n0 = nt * NT, H0 = nt * 32;

    unsigned round = 0;
    float acc[2][8][4];

    for (int t = 0; t < T_STEPS; t++) {
        const int rb = t & 1, wb = rb ^ 1;
        if (t > 0) out_calc(t - 1, g_h2[rb], Wlin, blin, out, ct);

        // ---- phase A: gates1 = [x_t, h1] @ W1p^T  (20 chunks, 10 per group) ----
        {
            Src sa;
            sa.a0 = signal + ((size_t)t * BATCH + m0) * FEAT; sa.lda0 = FEAT; sa.split = FEAT / 32;
            sa.a1 = g_h1[rb] + (size_t)m0 * HID;              sa.lda1 = HID;
            sa.B  = g_Wp1 + (size_t)n0 * K1;                  sa.ldb  = K1;
            const int half = (K1 / 32) / 2;                   // 10
            run_phase(sa, g * half, half, gbase_f, gbase_u, tid_g, lane, wy2, wx2, barid, acc);
        }
        epilogue(acc, smf, g, lane, wy2, wx2, g_b1, n0, g_c1, g_h1[wb], m0, H0);
        grid_sync(++round);

        // ---- phase B: gates2 = [h1', h2] @ W2p^T  (32 chunks, 16 per group) ----
        {
            Src sb;
            sb.a0 = g_h1[wb] + (size_t)m0 * HID; sb.lda0 = HID; sb.split = HID / 32;
            sb.a1 = g_h2[rb] + (size_t)m0 * HID; sb.lda1 = HID;
            sb.B  = g_Wp2 + (size_t)n0 * K2;     sb.ldb  = K2;
            const int half = (K2 / 32) / 2;                   // 16
            run_phase(sb, g * half, half, gbase_f, gbase_u, tid_g, lane, wy2, wx2, barid, acc);
        }
        epilogue(acc, smf, g, lane, wy2, wx2, g_b2, n0, g_c2, g_h2[wb], m0, H0);
        grid_sync(++round);
    }
    out_calc(T_STEPS - 1, g_h2[T_STEPS & 1], Wlin, blin, out, ct);
}

// --------------------------------- launcher ----------------------------------
extern "C" void kernel_launch(void* const* d_in, const int* in_sizes, int n_in,
                              void* d_out, int out_size) {
    const float* signal = (const float*)d_in[0];
    const float* Wih1   = (const float*)d_in[1];
    const float* Whh1   = (const float*)d_in[2];
    const float* bih1   = (const float*)d_in[3];
    const float* bhh1   = (const float*)d_in[4];
    const float* Wih2   = (const float*)d_in[5];
    const float* Whh2   = (const float*)d_in[6];
    const float* bih2   = (const float*)d_in[7];
    const float* bhh2   = (const float*)d_in[8];
    const float* Wlin   = (const float*)d_in[9];
    const float* blin   = (const float*)d_in[10];
    float* out = (float*)d_out;

    (void)in_sizes; (void)n_in; (void)out_size;

    cudaFuncSetAttribute(lstm_persistent,
                         cudaFuncAttributeMaxDynamicSharedMemorySize, SMEM_BYTES);

    prep_kernel<<<4096, 256>>>(Wih1, Whh1, bih1, bhh1, Wih2, Whh2, bih2, bhh2);
    lstm_persistent<<<NCTA, NTHREADS, SMEM_BYTES>>>(signal, Wlin, blin, out);
}

// round 5
// speedup vs baseline: 1.8286x; 1.7117x over previous
#include <cuda_runtime.h>
#include <cuda_fp16.h>
#include <cstdint>

#define T_STEPS 512
#define BATCH   512
#define FEAT    128
#define HID     512
#define TAGS    2
#define NG      2048          // 4*HID
#define K1      640           // FEAT + HID
#define K2      1024          // HID + HID
#define NCTA    128
#define MT      64
#define NT      128
#define KC      64            // halves per K-chunk (128B per row)
#define NTHREADS 256          // 8 warps: 2 K-groups x 4 warps

// stage layout (bytes): A 64 rows x 128B = 8192, B 128 rows x 128B = 16384
#define A_BYTES     8192
#define STAGE_BYTES 24576
#define GROUP_BYTES (4 * STAGE_BYTES)           // 98304 (4 stages)
#define SMEM_BYTES  (2 * GROUP_BYTES)           // 196608

// ------------------------- device globals (scratch) -------------------------
__device__ __half g_Wp1h[NG * K1];       // permuted [n][k], fp16
__device__ __half g_Wp2h[NG * K2];
__device__ float  g_b1[NG];
__device__ float  g_b2[NG];
__device__ __half g_sigh[T_STEPS * BATCH * FEAT];
__device__ __half g_h1[2][BATCH * HID];
__device__ __half g_h2[2][BATCH * HID];
__device__ float  g_c1[BATCH * HID];
__device__ float  g_c2[BATCH * HID];
__device__ unsigned g_bar;
__device__ unsigned g_gen;

// ------------------------------- helpers ------------------------------------
__device__ __forceinline__ float sigm(float x) { return 1.0f / (1.0f + __expf(-x)); }
__device__ __forceinline__ void cp16(uint32_t dst, const void* src) {
    asm volatile("cp.async.cg.shared.global [%0], [%1], 16;\n" :: "r"(dst), "l"(src));
}
#define CPA_COMMIT() asm volatile("cp.async.commit_group;\n")
#define CPA_WAIT2()  asm volatile("cp.async.wait_group 2;\n")
#define GBAR(id)     asm volatile("bar.sync %0, %1;" :: "r"(id), "r"(128) : "memory")

__device__ __forceinline__ unsigned ld_acq(const unsigned* p) {
    unsigned v;
    asm volatile("ld.acquire.gpu.u32 %0, [%1];" : "=r"(v) : "l"(p) : "memory");
    return v;
}

// swizzled 4B shared load (region-relative 128B-row XOR swizzle)
__device__ __forceinline__ unsigned lds_sw(const char* base, int row, int colh) {
    uint32_t off = (uint32_t)(row * 128 + colh * 2);
    off ^= (off >> 3) & 0x70u;
    return *(const uint32_t*)(base + off);
}

// permuted column index n -> original gate row
__device__ __forceinline__ int orig_row(long n) {
    int chunk = (int)(n >> 7), w = (int)(n & 127);
    int q = w >> 5, r = w & 31;
    return q * HID + chunk * 32 + r;
}

// ------------------------------ prep kernel ---------------------------------
__global__ void prep_kernel(const float* __restrict__ signal,
                            const float* __restrict__ Wih1, const float* __restrict__ Whh1,
                            const float* __restrict__ bih1, const float* __restrict__ bhh1,
                            const float* __restrict__ Wih2, const float* __restrict__ Whh2,
                            const float* __restrict__ bih2, const float* __restrict__ bhh2) {
    const long NW1 = (long)NG * K1;
    const long NW2 = (long)NG * K2;
    const long NSIG = (long)T_STEPS * BATCH * FEAT;
    const long NH   = (long)BATCH * HID;
    const long TOT = NW1 + NW2 + 2L * NG + NSIG + 6L * NH;
    for (long i = blockIdx.x * (long)blockDim.x + threadIdx.x; i < TOT;
         i += (long)gridDim.x * blockDim.x) {
        if (i < NW1) {
            long n = i / K1, k = i % K1;
            int o = orig_row(n);
            float v = (k < FEAT) ? Wih1[(long)o * FEAT + k]
                                 : Whh1[(long)o * HID + (k - FEAT)];
            g_Wp1h[i] = __float2half_rn(v);
        } else if (i < NW1 + NW2) {
            long j = i - NW1;
            long n = j / K2, k = j % K2;
            int o = orig_row(n);
            float v = (k < HID) ? Wih2[(long)o * HID + k]
                                : Whh2[(long)o * HID + (k - HID)];
            g_Wp2h[j] = __float2half_rn(v);
        } else if (i < NW1 + NW2 + NG) {
            long n = i - NW1 - NW2;
            int o = orig_row(n);
            g_b1[n] = bih1[o] + bhh1[o];
        } else if (i < NW1 + NW2 + 2L * NG) {
            long n = i - NW1 - NW2 - NG;
            int o = orig_row(n);
            g_b2[n] = bih2[o] + bhh2[o];
        } else if (i < NW1 + NW2 + 2L * NG + NSIG) {
            long j = i - NW1 - NW2 - 2L * NG;
            g_sigh[j] = __float2half_rn(signal[j]);
        } else {
            long j = i - (NW1 + NW2 + 2L * NG + NSIG);
            long seg = j / NH, o = j % NH;
            if      (seg == 0) g_h1[0][o] = __float2half_rn(0.f);
            else if (seg == 1) g_h1[1][o] = __float2half_rn(0.f);
            else if (seg == 2) g_h2[0][o] = __float2half_rn(0.f);
            else if (seg == 3) g_h2[1][o] = __float2half_rn(0.f);
            else if (seg == 4) g_c1[o]    = 0.f;
            else               g_c2[o]    = 0.f;
        }
    }
    if (blockIdx.x == 0 && threadIdx.x == 0) { g_bar = 0u; g_gen = 0u; }
}

// ------------------------------ grid barrier --------------------------------
__device__ __forceinline__ void grid_sync(unsigned target) {
    __syncthreads();
    if (threadIdx.x == 0) {
        __threadfence();
        unsigned a = atomicAdd(&g_bar, 1u);
        if (a == NCTA - 1u) {
            atomicExch(&g_bar, 0u);
            __threadfence();
            atomicAdd(&g_gen, 1u);
        } else {
            while (ld_acq(&g_gen) < target) __nanosleep(64);
        }
        __threadfence();
    }
    __syncthreads();
}

// --------------------------------- GEMM -------------------------------------
struct Src {
    const __half* a0; int lda0; int split;   // global chunk idx < split -> a0
    const __half* a1; int lda1;              // otherwise a1
    const __half* B;  int ldb;
};

__device__ __forceinline__ void issue_chunk(const Src& s, int ck, uint32_t gbase_u,
                                            int st, int tid_g) {
    // A tile: 64 rows x 128B; 2 threads/row, 64B each (4 x cp16)
    {
        int row = tid_g & 63, seg = tid_g >> 6;
        const __half* src = (ck < s.split)
            ? s.a0 + (size_t)row * s.lda0 + ck * KC + seg * 32
            : s.a1 + (size_t)row * s.lda1 + (ck - s.split) * KC + seg * 32;
        uint32_t rb = (uint32_t)(row * 128 + seg * 64);
        #pragma unroll
        for (int j = 0; j < 4; j++) {
            uint32_t off = rb + j * 16;
            off ^= (off >> 3) & 0x70u;
            cp16(gbase_u + st * STAGE_BYTES + off, src + j * 8);
        }
    }
    // B tile: 128 rows x 128B; 1 row/thread (8 x cp16)
    {
        const __half* src = s.B + (size_t)tid_g * s.ldb + ck * KC;
        uint32_t rb = (uint32_t)(tid_g * 128);
        #pragma unroll
        for (int j = 0; j < 8; j++) {
            uint32_t off = rb + j * 16;
            off ^= (off >> 3) & 0x70u;
            cp16(gbase_u + st * STAGE_BYTES + A_BYTES + off, src + j * 8);
        }
    }
    CPA_COMMIT();
}

// one K-group runs its chunks through a 4-stage pipeline, 1 barrier per iter
__device__ __forceinline__ void run_phase(const Src s, int ckbase, int nch,
                                          const char* gbase_c, uint32_t gbase_u,
                                          int tid_g, int lane, int wy2, int wx2,
                                          int barid, float acc[2][8][4]) {
    #pragma unroll
    for (int mi = 0; mi < 2; mi++)
        #pragma unroll
        for (int ni = 0; ni < 8; ni++)
            #pragma unroll
            for (int r = 0; r < 4; r++) acc[mi][ni][r] = 0.f;

    const int lq = lane >> 2, lr = lane & 3;

    issue_chunk(s, ckbase + 0, gbase_u, 0, tid_g);
    issue_chunk(s, ckbase + 1, gbase_u, 1, tid_g);

    for (int i = 0; i < nch; i++) {
        if (i + 2 < nch) issue_chunk(s, ckbase + i + 2, gbase_u, (i + 2) & 3, tid_g);
        else             CPA_COMMIT();          // dummy keeps wait counting aligned
        CPA_WAIT2();
        GBAR(barid);                            // visibility + stage-reuse ordering
        const char* sA = gbase_c + (size_t)(i & 3) * STAGE_BYTES;
        const char* sB = sA + A_BYTES;
        #pragma unroll
        for (int kk = 0; kk < 4; kk++) {        // 4 x k16 per 64-chunk
            const int kb = kk * 16;
            unsigned a[2][4];
            #pragma unroll
            for (int mi = 0; mi < 2; mi++) {
                int row = wy2 * 32 + mi * 16 + lq;
                a[mi][0] = lds_sw(sA, row,     kb + 2 * lr);
                a[mi][1] = lds_sw(sA, row + 8, kb + 2 * lr);
                a[mi][2] = lds_sw(sA, row,     kb + 8 + 2 * lr);
                a[mi][3] = lds_sw(sA, row + 8, kb + 8 + 2 * lr);
            }
            #pragma unroll
            for (int ni = 0; ni < 8; ni++) {
                int col = wx2 * 64 + ni * 8 + lq;
                unsigned b0 = lds_sw(sB, col, kb + 2 * lr);
                unsigned b1 = lds_sw(sB, col, kb + 8 + 2 * lr);
                #pragma unroll
                for (int mi = 0; mi < 2; mi++) {
                    asm volatile(
                        "mma.sync.aligned.m16n8k16.row.col.f32.f16.f16.f32 "
                        "{%0,%1,%2,%3}, {%4,%5,%6,%7}, {%8,%9}, {%0,%1,%2,%3};\n"
                        : "+f"(acc[mi][ni][0]), "+f"(acc[mi][ni][1]),
                          "+f"(acc[mi][ni][2]), "+f"(acc[mi][ni][3])
                        : "r"(a[mi][0]), "r"(a[mi][1]), "r"(a[mi][2]), "r"(a[mi][3]),
                          "r"(b0), "r"(b1));
                }
            }
        }
    }
    GBAR(barid);    // all group warps done with stages before epilogue reuses them
}

// ------------------------------ LSTM epilogue --------------------------------
__device__ __forceinline__ void epilogue(float acc[2][8][4], char* smc,
                                         int g, int lane, int wy2, int wx2,
                                         const float* __restrict__ bias, int n0,
                                         float* __restrict__ cbuf,
                                         __half* __restrict__ hout,
                                         int m0, int H0) {
    float* buf = (float*)(smc + (size_t)g * GROUP_BYTES);
    const int lq = lane >> 2, lr = lane & 3;
    #pragma unroll
    for (int mi = 0; mi < 2; mi++) {
        #pragma unroll
        for (int ni = 0; ni < 8; ni++) {
            int row = wy2 * 32 + mi * 16 + lq;
            int col = wx2 * 64 + ni * 8 + 2 * lr;
            buf[row * 132 + col]           = acc[mi][ni][0];
            buf[row * 132 + col + 1]       = acc[mi][ni][1];
            buf[(row + 8) * 132 + col]     = acc[mi][ni][2];
            buf[(row + 8) * 132 + col + 1] = acc[mi][ni][3];
        }
    }
    __syncthreads();
    const float* b0 = (const float*)smc;
    const float* b1 = (const float*)(smc + GROUP_BYTES);
    const int tid = threadIdx.x;
    #pragma unroll
    for (int it = 0; it < (MT * 32) / NTHREADS; it++) {
        int p  = it * NTHREADS + tid;
        int bl = p >> 5, r = p & 31;
        float gi = b0[bl * 132 + r]      + b1[bl * 132 + r]      + __ldg(bias + n0 + r);
        float gf = b0[bl * 132 + 32 + r] + b1[bl * 132 + 32 + r] + __ldg(bias + n0 + 32 + r);
        float gg = b0[bl * 132 + 64 + r] + b1[bl * 132 + 64 + r] + __ldg(bias + n0 + 64 + r);
        float go = b0[bl * 132 + 96 + r] + b1[bl * 132 + 96 + r] + __ldg(bias + n0 + 96 + r);
        int gidx = (m0 + bl) * HID + H0 + r;
        float c  = cbuf[gidx];
        float cn = sigm(gf) * c + sigm(gi) * tanhf(gg);
        cbuf[gidx] = cn;
        hout[gidx] = __float2half_rn(sigm(go) * tanhf(cn));
    }
}

// ----------------------------- output projection -----------------------------
__device__ __forceinline__ void out_calc(int tp, const __half* __restrict__ h2cur,
                                         const float* __restrict__ Wlin,
                                         const float* __restrict__ blin,
                                         float* __restrict__ out, int ct) {
    const int tid = threadIdx.x, lane = tid & 31, wid = tid >> 5;
    if (wid >= 4) return;
    const int b = ct * 4 + wid;                     // 128 CTAs x 4 rows = 512
    const __half* hrow = h2cur + (size_t)b * HID;
    float s0 = 0.f, s1 = 0.f;
    #pragma unroll 8
    for (int k = lane; k < HID; k += 32) {
        float hv = __half2float(__ldcg(hrow + k));  // bypass L1 (cross-CTA writer)
        s0 += hv * __ldg(Wlin + k);
        s1 += hv * __ldg(Wlin + HID + k);
    }
    #pragma unroll
    for (int o = 16; o; o >>= 1) {
        s0 += __shfl_xor_sync(0xffffffffu, s0, o);
        s1 += __shfl_xor_sync(0xffffffffu, s1, o);
    }
    if (lane == 0) {
        out[(size_t)b * (T_STEPS * TAGS) + tp * TAGS + 0] = s0 + blin[0];
        out[(size_t)b * (T_STEPS * TAGS) + tp * TAGS + 1] = s1 + blin[1];
    }
}

// ------------------------------ persistent kernel ----------------------------
__global__ void __launch_bounds__(NTHREADS, 1)
lstm_persistent(const float* __restrict__ Wlin, const float* __restrict__ blin,
                float* __restrict__ out) {
    extern __shared__ char smc[];
    const uint32_t smu = (uint32_t)__cvta_generic_to_shared(smc);
    const int tid = threadIdx.x;
    const int g = tid >> 7;                 // K-group 0/1
    const int tid_g = tid & 127;
    const int lane = tid & 31;
    const int wig = tid_g >> 5;             // warp in group 0..3
    const int wy2 = wig >> 1, wx2 = wig & 1;
    const int barid = 1 + g;
    const char* gbase_c = smc + (size_t)g * GROUP_BYTES;
    const uint32_t gbase_u = smu + (uint32_t)g * GROUP_BYTES;

    const int ct = blockIdx.x;
    const int mt = ct >> 4, nt = ct & 15;   // 8 M-tiles x 16 N-tiles
    const int m0 = mt * MT, n0 = nt * NT, H0 = nt * 32;

    unsigned round = 0;
    float acc[2][8][4];

    for (int t = 0; t < T_STEPS; t++) {
        const int rb = t & 1, wb = rb ^ 1;
        if (t > 0) out_calc(t - 1, g_h2[rb], Wlin, blin, out, ct);

        // ---- phase A: gates1 = [x_t, h1] @ W1p^T  (10 chunks of 64, 5/group) ----
        {
            Src sa;
            sa.a0 = g_sigh + ((size_t)t * BATCH + m0) * FEAT; sa.lda0 = FEAT;
            sa.split = FEAT / KC;                             // 2
            sa.a1 = g_h1[rb] + (size_t)m0 * HID;              sa.lda1 = HID;
            sa.B  = g_Wp1h + (size_t)n0 * K1;                 sa.ldb  = K1;
            const int half = (K1 / KC) / 2;                   // 5
            run_phase(sa, g * half, half, gbase_c, gbase_u, tid_g, lane, wy2, wx2, barid, acc);
        }
        epilogue(acc, smc, g, lane, wy2, wx2, g_b1, n0, g_c1, g_h1[wb], m0, H0);
        grid_sync(++round);

        // ---- phase B: gates2 = [h1', h2] @ W2p^T  (16 chunks of 64, 8/group) ----
        {
            Src sb;
            sb.a0 = g_h1[wb] + (size_t)m0 * HID; sb.lda0 = HID; sb.split = HID / KC; // 8
            sb.a1 = g_h2[rb] + (size_t)m0 * HID; sb.lda1 = HID;
            sb.B  = g_Wp2h + (size_t)n0 * K2;    sb.ldb  = K2;
            const int half = (K2 / KC) / 2;                   // 8
            run_phase(sb, g * half, half, gbase_c, gbase_u, tid_g, lane, wy2, wx2, barid, acc);
        }
        epilogue(acc, smc, g, lane, wy2, wx2, g_b2, n0, g_c2, g_h2[wb], m0, H0);
        grid_sync(++round);
    }
    out_calc(T_STEPS - 1, g_h2[T_STEPS & 1], Wlin, blin, out, ct);
}

// --------------------------------- launcher ----------------------------------
extern "C" void kernel_launch(void* const* d_in, const int* in_sizes, int n_in,
                              void* d_out, int out_size) {
    const float* signal = (const float*)d_in[0];
    const float* Wih1   = (const float*)d_in[1];
    const float* Whh1   = (const float*)d_in[2];
    const float* bih1   = (const float*)d_in[3];
    const float* bhh1   = (const float*)d_in[4];
    const float* Wih2   = (const float*)d_in[5];
    const float* Whh2   = (const float*)d_in[6];
    const float* bih2   = (const float*)d_in[7];
    const float* bhh2   = (const float*)d_in[8];
    const float* Wlin   = (const float*)d_in[9];
    const float* blin   = (const float*)d_in[10];
    float* out = (float*)d_out;

    (void)in_sizes; (void)n_in; (void)out_size;

    cudaFuncSetAttribute(lstm_persistent,
                         cudaFuncAttributeMaxDynamicSharedMemorySize, SMEM_BYTES);

    prep_kernel<<<4096, 256>>>(signal, Wih1, Whh1, bih1, bhh1,
                               Wih2, Whh2, bih2, bhh2);
    lstm_persistent<<<NCTA, NTHREADS, SMEM_BYTES>>>(Wlin, blin, out);
}

// round 6
// speedup vs baseline: 2.0235x; 1.1066x over previous
#include <cuda_runtime.h>
#include <cuda_fp16.h>
#include <cstdint>

#define T_STEPS 512
#define BATCH   512
#define FEAT    128
#define HID     512
#define TAGS    2
#define NG      2048          // 4*HID
#define K1      640           // FEAT + HID
#define K2      1024          // HID + HID
#define NCTA    128
#define MT      64
#define NT      128
#define KC      64            // halves per K-chunk (128B per row)
#define NTHREADS 256          // 8 warps: 2 K-groups x 4 warps
#define NTGROUP 16            // CTAs per M-tile group

// stage layout (bytes): A 64 rows x 128B = 8192, B 128 rows x 128B = 16384
#define A_BYTES     8192
#define STAGE_BYTES 24576
#define GROUP_BYTES (4 * STAGE_BYTES)           // 98304 (4 stages)
#define SMEM_BYTES  (2 * GROUP_BYTES)           // 196608

// ------------------------- device globals (scratch) -------------------------
__device__ __half g_Wp1h[NG * K1];       // permuted [n][k], fp16
__device__ __half g_Wp2h[NG * K2];
__device__ float  g_b1[NG];
__device__ float  g_b2[NG];
__device__ __half g_sigh[T_STEPS * BATCH * FEAT];
__device__ __half g_h1[2][BATCH * HID];
__device__ __half g_h2[2][BATCH * HID];
__device__ float  g_c1[BATCH * HID];
__device__ float  g_c2[BATCH * HID];
__device__ unsigned g_bar8[8];
__device__ unsigned g_gen8[8];

// ------------------------------- helpers ------------------------------------
__device__ __forceinline__ float sigm(float x) { return 1.0f / (1.0f + __expf(-x)); }
__device__ __forceinline__ void cp16(uint32_t dst, const void* src) {
    asm volatile("cp.async.cg.shared.global [%0], [%1], 16;\n" :: "r"(dst), "l"(src));
}
#define CPA_COMMIT() asm volatile("cp.async.commit_group;\n")
#define CPA_WAIT2()  asm volatile("cp.async.wait_group 2;\n")
#define GBAR(id)     asm volatile("bar.sync %0, %1;" :: "r"(id), "r"(128) : "memory")
#define LDSM4(r0, r1, r2, r3, addr)                                            \
    asm volatile("ldmatrix.sync.aligned.m8n8.x4.shared.b16 {%0,%1,%2,%3}, [%4];" \
        : "=r"(r0), "=r"(r1), "=r"(r2), "=r"(r3) : "r"(addr))

__device__ __forceinline__ unsigned ld_acq(const unsigned* p) {
    unsigned v;
    asm volatile("ld.acquire.gpu.u32 %0, [%1];" : "=r"(v) : "l"(p) : "memory");
    return v;
}

// permuted column index n -> original gate row
__device__ __forceinline__ int orig_row(long n) {
    int chunk = (int)(n >> 7), w = (int)(n & 127);
    int q = w >> 5, r = w & 31;
    return q * HID + chunk * 32 + r;
}

// ------------------------------ prep kernel ---------------------------------
__global__ void prep_kernel(const float* __restrict__ signal,
                            const float* __restrict__ Wih1, const float* __restrict__ Whh1,
                            const float* __restrict__ bih1, const float* __restrict__ bhh1,
                            const float* __restrict__ Wih2, const float* __restrict__ Whh2,
                            const float* __restrict__ bih2, const float* __restrict__ bhh2) {
    const long NW1 = (long)NG * K1;
    const long NW2 = (long)NG * K2;
    const long NSIG = (long)T_STEPS * BATCH * FEAT;
    const long NH   = (long)BATCH * HID;
    const long TOT = NW1 + NW2 + 2L * NG + NSIG + 6L * NH;
    for (long i = blockIdx.x * (long)blockDim.x + threadIdx.x; i < TOT;
         i += (long)gridDim.x * blockDim.x) {
        if (i < NW1) {
            long n = i / K1, k = i % K1;
            int o = orig_row(n);
            float v = (k < FEAT) ? Wih1[(long)o * FEAT + k]
                                 : Whh1[(long)o * HID + (k - FEAT)];
            g_Wp1h[i] = __float2half_rn(v);
        } else if (i < NW1 + NW2) {
            long j = i - NW1;
            long n = j / K2, k = j % K2;
            int o = orig_row(n);
            float v = (k < HID) ? Wih2[(long)o * HID + k]
                                : Whh2[(long)o * HID + (k - HID)];
            g_Wp2h[j] = __float2half_rn(v);
        } else if (i < NW1 + NW2 + NG) {
            long n = i - NW1 - NW2;
            int o = orig_row(n);
            g_b1[n] = bih1[o] + bhh1[o];
        } else if (i < NW1 + NW2 + 2L * NG) {
            long n = i - NW1 - NW2 - NG;
            int o = orig_row(n);
            g_b2[n] = bih2[o] + bhh2[o];
        } else if (i < NW1 + NW2 + 2L * NG + NSIG) {
            long j = i - NW1 - NW2 - 2L * NG;
            g_sigh[j] = __float2half_rn(signal[j]);
        } else {
            long j = i - (NW1 + NW2 + 2L * NG + NSIG);
            long seg = j / NH, o = j % NH;
            if      (seg == 0) g_h1[0][o] = __float2half_rn(0.f);
            else if (seg == 1) g_h1[1][o] = __float2half_rn(0.f);
            else if (seg == 2) g_h2[0][o] = __float2half_rn(0.f);
            else if (seg == 3) g_h2[1][o] = __float2half_rn(0.f);
            else if (seg == 4) g_c1[o]    = 0.f;
            else               g_c2[o]    = 0.f;
        }
    }
    if (blockIdx.x == 0 && threadIdx.x < 8) {
        g_bar8[threadIdx.x] = 0u;
        g_gen8[threadIdx.x] = 0u;
    }
}

// --------------------- per-M-tile group barrier (16 CTAs) --------------------
__device__ __forceinline__ void group_sync(int mt, unsigned target) {
    __syncthreads();
    if (threadIdx.x == 0) {
        __threadfence();
        unsigned a = atomicAdd(&g_bar8[mt], 1u);
        if (a == NTGROUP - 1u) {
            atomicExch(&g_bar8[mt], 0u);
            __threadfence();
            atomicAdd(&g_gen8[mt], 1u);
        } else {
            while (ld_acq(&g_gen8[mt]) < target) { }
        }
        __threadfence();
    }
    __syncthreads();
}

// --------------------------------- GEMM -------------------------------------
struct Src {
    const __half* a0; int lda0; int split;   // global chunk idx < split -> a0
    const __half* a1; int lda1;              // otherwise a1
    const __half* B;  int ldb;
};

__device__ __forceinline__ void issue_chunk(const Src& s, int ck, uint32_t gbase_u,
                                            int st, int tid_g) {
    // A tile: 64 rows x 128B; 2 threads/row, 64B each (4 x cp16)
    {
        int row = tid_g & 63, seg = tid_g >> 6;
        const __half* src = (ck < s.split)
            ? s.a0 + (size_t)row * s.lda0 + ck * KC + seg * 32
            : s.a1 + (size_t)row * s.lda1 + (ck - s.split) * KC + seg * 32;
        uint32_t rb = (uint32_t)(row * 128 + seg * 64);
        #pragma unroll
        for (int j = 0; j < 4; j++) {
            uint32_t off = rb + j * 16;
            off ^= (off >> 3) & 0x70u;
            cp16(gbase_u + st * STAGE_BYTES + off, src + j * 8);
        }
    }
    // B tile: 128 rows x 128B; 1 row/thread (8 x cp16)
    {
        const __half* src = s.B + (size_t)tid_g * s.ldb + ck * KC;
        uint32_t rb = (uint32_t)(tid_g * 128);
        #pragma unroll
        for (int j = 0; j < 8; j++) {
            uint32_t off = rb + j * 16;
            off ^= (off >> 3) & 0x70u;
            cp16(gbase_u + st * STAGE_BYTES + A_BYTES + off, src + j * 8);
        }
    }
    CPA_COMMIT();
}

// one K-group runs its chunks through a 4-stage pipeline, 1 barrier per iter
__device__ __forceinline__ void run_phase(const Src s, int ckbase, int nch,
                                          uint32_t gbase_u,
                                          int tid_g, int lane, int wy2, int wx2,
                                          int barid, float acc[2][8][4]) {
    #pragma unroll
    for (int mi = 0; mi < 2; mi++)
        #pragma unroll
        for (int ni = 0; ni < 8; ni++)
            #pragma unroll
            for (int r = 0; r < 4; r++) acc[mi][ni][r] = 0.f;

    // per-thread ldmatrix in-tile byte offsets (before swizzle)
    const uint32_t a_off0 = (uint32_t)((wy2 * 32 + (lane & 15)) * 128
                                       + ((lane >> 4) * 8) * 2);
    const uint32_t b_off0 = (uint32_t)((wx2 * 64 + ((lane >> 4) & 1) * 8 + (lane & 7)) * 128
                                       + (((lane >> 3) & 1) * 8) * 2);

    issue_chunk(s, ckbase + 0, gbase_u, 0, tid_g);
    issue_chunk(s, ckbase + 1, gbase_u, 1, tid_g);

    for (int i = 0; i < nch; i++) {
        if (i + 2 < nch) issue_chunk(s, ckbase + i + 2, gbase_u, (i + 2) & 3, tid_g);
        else             CPA_COMMIT();          // dummy keeps wait counting aligned
        CPA_WAIT2();
        GBAR(barid);                            // visibility + stage-reuse ordering
        const uint32_t stA = gbase_u + (uint32_t)(i & 3) * STAGE_BYTES;
        const uint32_t stB = stA + A_BYTES;
        #pragma unroll
        for (int kk = 0; kk < 4; kk++) {        // 4 x k16 per 64-chunk
            const uint32_t kbb = (uint32_t)(kk * 32);   // 16 halves = 32 bytes
            unsigned a[2][4], b[4][4];
            #pragma unroll
            for (int mi = 0; mi < 2; mi++) {
                uint32_t off = a_off0 + (uint32_t)(mi * 16 * 128) + kbb;
                off ^= (off >> 3) & 0x70u;
                LDSM4(a[mi][0], a[mi][1], a[mi][2], a[mi][3], stA + off);
            }
            #pragma unroll
            for (int p = 0; p < 4; p++) {
                uint32_t off = b_off0 + (uint32_t)(p * 16 * 128) + kbb;
                off ^= (off >> 3) & 0x70u;
                LDSM4(b[p][0], b[p][1], b[p][2], b[p][3], stB + off);
            }
            #pragma unroll
            for (int ni = 0; ni < 8; ni++) {
                const int p = ni >> 1, hi = (ni & 1) * 2;
                #pragma unroll
                for (int mi = 0; mi < 2; mi++) {
                    asm volatile(
                        "mma.sync.aligned.m16n8k16.row.col.f32.f16.f16.f32 "
                        "{%0,%1,%2,%3}, {%4,%5,%6,%7}, {%8,%9}, {%0,%1,%2,%3};\n"
                        : "+f"(acc[mi][ni][0]), "+f"(acc[mi][ni][1]),
                          "+f"(acc[mi][ni][2]), "+f"(acc[mi][ni][3])
                        : "r"(a[mi][0]), "r"(a[mi][1]), "r"(a[mi][2]), "r"(a[mi][3]),
                          "r"(b[p][hi]), "r"(b[p][hi + 1]));
                }
            }
        }
    }
    GBAR(barid);    // all group warps done with stages before epilogue reuses them
}

// ------------------------------ LSTM epilogue --------------------------------
__device__ __forceinline__ void epilogue(float acc[2][8][4], char* smc,
                                         int g, int lane, int wy2, int wx2,
                                         const float* __restrict__ bias, int n0,
                                         float* __restrict__ cbuf,
                                         __half* __restrict__ hout,
                                         int m0, int H0) {
    float* buf = (float*)(smc + (size_t)g * GROUP_BYTES);
    const int lq = lane >> 2, lr = lane & 3;
    #pragma unroll
    for (int mi = 0; mi < 2; mi++) {
        #pragma unroll
        for (int ni = 0; ni < 8; ni++) {
            int row = wy2 * 32 + mi * 16 + lq;
            int col = wx2 * 64 + ni * 8 + 2 * lr;
            buf[row * 132 + col]           = acc[mi][ni][0];
            buf[row * 132 + col + 1]       = acc[mi][ni][1];
            buf[(row + 8) * 132 + col]     = acc[mi][ni][2];
            buf[(row + 8) * 132 + col + 1] = acc[mi][ni][3];
        }
    }
    __syncthreads();
    const float* b0 = (const float*)smc;
    const float* b1 = (const float*)(smc + GROUP_BYTES);
    const int tid = threadIdx.x;
    #pragma unroll
    for (int it = 0; it < (MT * 32) / NTHREADS; it++) {
        int p  = it * NTHREADS + tid;
        int bl = p >> 5, r = p & 31;
        float gi = b0[bl * 132 + r]      + b1[bl * 132 + r]      + __ldg(bias + n0 + r);
        float gf = b0[bl * 132 + 32 + r] + b1[bl * 132 + 32 + r] + __ldg(bias + n0 + 32 + r);
        float gg = b0[bl * 132 + 64 + r] + b1[bl * 132 + 64 + r] + __ldg(bias + n0 + 64 + r);
        float go = b0[bl * 132 + 96 + r] + b1[bl * 132 + 96 + r] + __ldg(bias + n0 + 96 + r);
        int gidx = (m0 + bl) * HID + H0 + r;
        float c  = cbuf[gidx];
        float cn = sigm(gf) * c + sigm(gi) * tanhf(gg);
        cbuf[gidx] = cn;
        hout[gidx] = __float2half_rn(sigm(go) * tanhf(cn));
    }
}

// ----------------------------- output projection -----------------------------
__device__ __forceinline__ void out_calc(int tp, const __half* __restrict__ h2cur,
                                         const float* __restrict__ Wlin,
                                         const float* __restrict__ blin,
                                         float* __restrict__ out, int ct) {
    const int tid = threadIdx.x, lane = tid & 31, wid = tid >> 5;
    if (wid >= 4) return;
    const int b = ct * 4 + wid;                     // 128 CTAs x 4 rows = 512
    const __half* hrow = h2cur + (size_t)b * HID;
    float s0 = 0.f, s1 = 0.f;
    #pragma unroll 8
    for (int k = lane; k < HID; k += 32) {
        float hv = __half2float(__ldcg(hrow + k));  // bypass L1 (cross-CTA writer)
        s0 += hv * __ldg(Wlin + k);
        s1 += hv * __ldg(Wlin + HID + k);
    }
    #pragma unroll
    for (int o = 16; o; o >>= 1) {
        s0 += __shfl_xor_sync(0xffffffffu, s0, o);
        s1 += __shfl_xor_sync(0xffffffffu, s1, o);
    }
    if (lane == 0) {
        out[(size_t)b * (T_STEPS * TAGS) + tp * TAGS + 0] = s0 + blin[0];
        out[(size_t)b * (T_STEPS * TAGS) + tp * TAGS + 1] = s1 + blin[1];
    }
}

// ------------------------------ persistent kernel ----------------------------
__global__ void __launch_bounds__(NTHREADS, 1)
lstm_persistent(const float* __restrict__ Wlin, const float* __restrict__ blin,
                float* __restrict__ out) {
    extern __shared__ char smc[];
    const uint32_t smu = (uint32_t)__cvta_generic_to_shared(smc);
    const int tid = threadIdx.x;
    const int g = tid >> 7;                 // K-group 0/1
    const int tid_g = tid & 127;
    const int lane = tid & 31;
    const int wig = tid_g >> 5;             // warp in group 0..3
    const int wy2 = wig >> 1, wx2 = wig & 1;
    const int barid = 1 + g;
    const uint32_t gbase_u = smu + (uint32_t)g * GROUP_BYTES;

    const int ct = blockIdx.x;
    const int mt = ct >> 4, nt = ct & 15;   // 8 M-tiles x 16 N-tiles
    const int m0 = mt * MT, n0 = nt * NT, H0 = nt * 32;

    unsigned round = 0;
    float acc[2][8][4];

    for (int t = 0; t < T_STEPS; t++) {
        const int rb = t & 1, wb = rb ^ 1;
        if (t > 0) out_calc(t - 1, g_h2[rb], Wlin, blin, out, ct);

        // ---- phase A: gates1 = [x_t, h1] @ W1p^T  (10 chunks of 64, 5/group) ----
        {
            Src sa;
            sa.a0 = g_sigh + ((size_t)t * BATCH + m0) * FEAT; sa.lda0 = FEAT;
            sa.split = FEAT / KC;                             // 2
            sa.a1 = g_h1[rb] + (size_t)m0 * HID;              sa.lda1 = HID;
            sa.B  = g_Wp1h + (size_t)n0 * K1;                 sa.ldb  = K1;
            const int half = (K1 / KC) / 2;                   // 5
            run_phase(sa, g * half, half, gbase_u, tid_g, lane, wy2, wx2, barid, acc);
        }
        epilogue(acc, smc, g, lane, wy2, wx2, g_b1, n0, g_c1, g_h1[wb], m0, H0);
        group_sync(mt, ++round);

        // ---- phase B: gates2 = [h1', h2] @ W2p^T  (16 chunks of 64, 8/group) ----
        {
            Src sb;
            sb.a0 = g_h1[wb] + (size_t)m0 * HID; sb.lda0 = HID; sb.split = HID / KC; // 8
            sb.a1 = g_h2[rb] + (size_t)m0 * HID; sb.lda1 = HID;
            sb.B  = g_Wp2h + (size_t)n0 * K2;    sb.ldb  = K2;
            const int half = (K2 / KC) / 2;                   // 8
            run_phase(sb, g * half, half, gbase_u, tid_g, lane, wy2, wx2, barid, acc);
        }
        epilogue(acc, smc, g, lane, wy2, wx2, g_b2, n0, g_c2, g_h2[wb], m0, H0);
        group_sync(mt, ++round);
    }
    out_calc(T_STEPS - 1, g_h2[T_STEPS & 1], Wlin, blin, out, ct);
}

// --------------------------------- launcher ----------------------------------
extern "C" void kernel_launch(void* const* d_in, const int* in_sizes, int n_in,
                              void* d_out, int out_size) {
    const float* signal = (const float*)d_in[0];
    const float* Wih1   = (const float*)d_in[1];
    const float* Whh1   = (const float*)d_in[2];
    const float* bih1   = (const float*)d_in[3];
    const float* bhh1   = (const float*)d_in[4];
    const float* Wih2   = (const float*)d_in[5];
    const float* Whh2   = (const float*)d_in[6];
    const float* bih2   = (const float*)d_in[7];
    const float* bhh2   = (const float*)d_in[8];
    const float* Wlin   = (const float*)d_in[9];
    const float* blin   = (const float*)d_in[10];
    float* out = (float*)d_out;

    (void)in_sizes; (void)n_in; (void)out_size;

    cudaFuncSetAttribute(lstm_persistent,
                         cudaFuncAttributeMaxDynamicSharedMemorySize, SMEM_BYTES);

    prep_kernel<<<4096, 256>>>(signal, Wih1, Whh1, bih1, bhh1,
                               Wih2, Whh2, bih2, bhh2);
    lstm_persistent<<<NCTA, NTHREADS, SMEM_BYTES>>>(Wlin, blin, out);
}

// round 7
// speedup vs baseline: 2.7363x; 1.3522x over previous
#include <cuda_runtime.h>
#include <cuda_fp16.h>
#include <cstdint>

#define T_STEPS 512
#define BATCH   512
#define FEAT    128
#define HID     512
#define TAGS    2
#define NG      2048          // 4*HID
#define K1      640           // FEAT + HID
#define K2      1024          // HID + HID
#define NCTA    128
#define MT      128
#define NT      64
#define KC      64            // halves per K-chunk (128B rows)
#define NTHREADS 256          // 8 warps, warp tile 16x64
#define NTGROUP 32            // CTAs per M-group

// stages: A 128x128B = 16384, W 64x128B = 8192  -> 24576 each, 4 stages
#define A_BYTES     16384
#define STAGE_BYTES 24576
#define SM_W2       98304     // resident W2 slice: 64 x 1024 halves = 131072 B
#define SMEM_BYTES  229376    // 98304 + 131072

// ------------------------- device globals (scratch) -------------------------
__device__ __half g_Wp1h[NG * K1];       // permuted [n][k], fp16
__device__ __half g_Wp2h[NG * K2];
__device__ float  g_b1[NG];
__device__ float  g_b2[NG];
__device__ __half g_sigh[T_STEPS * BATCH * FEAT];
__device__ __half g_h1[2][BATCH * HID];
__device__ __half g_h2[2][BATCH * HID];
__device__ float  g_c1[BATCH * HID];
__device__ float  g_c2[BATCH * HID];
__device__ unsigned g_bar4[4];
__device__ unsigned g_gen4[4];

// ------------------------------- helpers ------------------------------------
__device__ __forceinline__ float sigm(float x) { return 1.0f / (1.0f + __expf(-x)); }
__device__ __forceinline__ void cp16(uint32_t dst, const void* src) {
    asm volatile("cp.async.cg.shared.global [%0], [%1], 16;\n" :: "r"(dst), "l"(src));
}
#define CPA_COMMIT() asm volatile("cp.async.commit_group;\n")
#define CPA_WAIT2()  asm volatile("cp.async.wait_group 2;\n")
#define CPA_WAIT0()  asm volatile("cp.async.wait_group 0;\n")
#define LDSM4(r0, r1, r2, r3, addr)                                            \
    asm volatile("ldmatrix.sync.aligned.m8n8.x4.shared.b16 {%0,%1,%2,%3}, [%4];" \
        : "=r"(r0), "=r"(r1), "=r"(r2), "=r"(r3) : "r"(addr))

__device__ __forceinline__ unsigned ld_acq(const unsigned* p) {
    unsigned v;
    asm volatile("ld.acquire.gpu.u32 %0, [%1];" : "=r"(v) : "l"(p) : "memory");
    return v;
}

// permuted column index n -> original gate row (gate-interleave of 16)
__device__ __forceinline__ int orig_row(long n) {
    int chunk = (int)(n >> 6), w = (int)(n & 63);
    int q = w >> 4, r = w & 15;
    return q * HID + chunk * 16 + r;
}

// ------------------------------ prep kernel ---------------------------------
__global__ void prep_kernel(const float* __restrict__ signal,
                            const float* __restrict__ Wih1, const float* __restrict__ Whh1,
                            const float* __restrict__ bih1, const float* __restrict__ bhh1,
                            const float* __restrict__ Wih2, const float* __restrict__ Whh2,
                            const float* __restrict__ bih2, const float* __restrict__ bhh2) {
    const long NW1 = (long)NG * K1;
    const long NW2 = (long)NG * K2;
    const long NSIG = (long)T_STEPS * BATCH * FEAT;
    const long NH   = (long)BATCH * HID;
    const long TOT = NW1 + NW2 + 2L * NG + NSIG + 6L * NH;
    for (long i = blockIdx.x * (long)blockDim.x + threadIdx.x; i < TOT;
         i += (long)gridDim.x * blockDim.x) {
        if (i < NW1) {
            long n = i / K1, k = i % K1;
            int o = orig_row(n);
            float v = (k < FEAT) ? Wih1[(long)o * FEAT + k]
                                 : Whh1[(long)o * HID + (k - FEAT)];
            g_Wp1h[i] = __float2half_rn(v);
        } else if (i < NW1 + NW2) {
            long j = i - NW1;
            long n = j / K2, k = j % K2;
            int o = orig_row(n);
            float v = (k < HID) ? Wih2[(long)o * HID + k]
                                : Whh2[(long)o * HID + (k - HID)];
            g_Wp2h[j] = __float2half_rn(v);
        } else if (i < NW1 + NW2 + NG) {
            long n = i - NW1 - NW2;
            int o = orig_row(n);
            g_b1[n] = bih1[o] + bhh1[o];
        } else if (i < NW1 + NW2 + 2L * NG) {
            long n = i - NW1 - NW2 - NG;
            int o = orig_row(n);
            g_b2[n] = bih2[o] + bhh2[o];
        } else if (i < NW1 + NW2 + 2L * NG + NSIG) {
            long j = i - NW1 - NW2 - 2L * NG;
            g_sigh[j] = __float2half_rn(signal[j]);
        } else {
            long j = i - (NW1 + NW2 + 2L * NG + NSIG);
            long seg = j / NH, o = j % NH;
            if      (seg == 0) g_h1[0][o] = __float2half_rn(0.f);
            else if (seg == 1) g_h1[1][o] = __float2half_rn(0.f);
            else if (seg == 2) g_h2[0][o] = __float2half_rn(0.f);
            else if (seg == 3) g_h2[1][o] = __float2half_rn(0.f);
            else if (seg == 4) g_c1[o]    = 0.f;
            else               g_c2[o]    = 0.f;
        }
    }
    if (blockIdx.x == 0 && threadIdx.x < 4) {
        g_bar4[threadIdx.x] = 0u;
        g_gen4[threadIdx.x] = 0u;
    }
}

// --------------------- per-M-group barrier (32 CTAs) -------------------------
__device__ __forceinline__ void group_sync(int mt, unsigned target) {
    __syncthreads();
    if (threadIdx.x == 0) {
        __threadfence();
        unsigned a = atomicAdd(&g_bar4[mt], 1u);
        if (a == NTGROUP - 1u) {
            atomicExch(&g_bar4[mt], 0u);
            __threadfence();
            atomicAdd(&g_gen4[mt], 1u);
        } else {
            while (ld_acq(&g_gen4[mt]) < target) { }
        }
        __threadfence();
    }
    __syncthreads();
}

// ------------------------------- GEMM pieces --------------------------------
struct Src {
    const __half* a0; int lda0; int split;   // chunk < split -> a0
    const __half* a1; int lda1;              // otherwise a1
    const __half* W;  int ldw;               // streamed weights (phase A) or null
};

__device__ __forceinline__ void issue_chunk(const Src& s, int ck, uint32_t smu,
                                            int st, int tid, bool streamW) {
    // A tile: 128 rows x 128B; 2 threads/row, 64B each (4 x cp16)
    {
        int row = tid >> 1, part = tid & 1;
        const __half* src = (ck < s.split)
            ? s.a0 + (size_t)row * s.lda0 + ck * KC + part * 32
            : s.a1 + (size_t)row * s.lda1 + (ck - s.split) * KC + part * 32;
        uint32_t rb = (uint32_t)(row * 128 + part * 64);
        #pragma unroll
        for (int j = 0; j < 4; j++) {
            uint32_t off = rb + j * 16;
            off ^= (off >> 3) & 0x70u;
            cp16(smu + st * STAGE_BYTES + off, src + j * 8);
        }
    }
    if (streamW) {
        // W tile: 64 rows x 128B; 4 threads/row, 32B each (2 x cp16)
        int row = tid >> 2, part = tid & 3;
        const __half* src = s.W + (size_t)row * s.ldw + ck * KC + part * 16;
        uint32_t rb = (uint32_t)(row * 128 + part * 32);
        #pragma unroll
        for (int j = 0; j < 2; j++) {
            uint32_t off = rb + j * 16;
            off ^= (off >> 3) & 0x70u;
            cp16(smu + st * STAGE_BYTES + A_BYTES + off, src + j * 8);
        }
    }
    CPA_COMMIT();
}

// one phase: nch chunks, 4-stage pipeline, 2-ahead, one bar per iter
__device__ __forceinline__ void run_phase(const Src s, int nch, uint32_t smu,
                                          int tid, int w, int lane, bool streamW,
                                          float acc[8][4]) {
    #pragma unroll
    for (int ni = 0; ni < 8; ni++)
        #pragma unroll
        for (int r = 0; r < 4; r++) acc[ni][r] = 0.f;

    const uint32_t a_off0 = (uint32_t)((w * 16 + (lane & 15)) * 128 + (lane >> 4) * 16);
    const uint32_t b_off0 = (uint32_t)(((((lane >> 4) & 1) * 8 + (lane & 7)) * 128)
                                       + ((lane >> 3) & 1) * 16);

    issue_chunk(s, 0, smu, 0, tid, streamW);
    issue_chunk(s, 1, smu, 1, tid, streamW);

    for (int i = 0; i < nch; i++) {
        if (i + 2 < nch) issue_chunk(s, i + 2, smu, (i + 2) & 3, tid, streamW);
        else             CPA_COMMIT();        // dummy keeps wait counting aligned
        CPA_WAIT2();
        __syncthreads();                      // data visible + stage-reuse ordering
        const uint32_t aA = smu + (uint32_t)(i & 3) * STAGE_BYTES;
        const uint32_t aW = streamW ? aA + A_BYTES
                                    : smu + SM_W2 + (uint32_t)i * 8192u;
        #pragma unroll
        for (int kk = 0; kk < 4; kk++) {
            uint32_t ao = a_off0 + (uint32_t)(kk * 32);
            ao ^= (ao >> 3) & 0x70u;
            unsigned a0, a1, a2, a3;
            LDSM4(a0, a1, a2, a3, aA + ao);
            unsigned b[4][4];
            #pragma unroll
            for (int p = 0; p < 4; p++) {
                uint32_t bo = b_off0 + (uint32_t)(p * 2048 + kk * 32);
                bo ^= (bo >> 3) & 0x70u;
                LDSM4(b[p][0], b[p][1], b[p][2], b[p][3], aW + bo);
            }
            #pragma unroll
            for (int ni = 0; ni < 8; ni++) {
                const int p = ni >> 1, hi = (ni & 1) * 2;
                asm volatile(
                    "mma.sync.aligned.m16n8k16.row.col.f32.f16.f16.f32 "
                    "{%0,%1,%2,%3}, {%4,%5,%6,%7}, {%8,%9}, {%0,%1,%2,%3};\n"
                    : "+f"(acc[ni][0]), "+f"(acc[ni][1]),
                      "+f"(acc[ni][2]), "+f"(acc[ni][3])
                    : "r"(a0), "r"(a1), "r"(a2), "r"(a3),
                      "r"(b[p][hi]), "r"(b[p][hi + 1]));
            }
        }
    }
}

// ------------------- register-local LSTM epilogue ----------------------------
// warp w owns rows m0+w*16..+15, all 64 gate-cols (4 gates x 16 h)
__device__ __forceinline__ void epilogue(const float acc[8][4],
                                         const float br[4][2][2],
                                         float* __restrict__ cbuf,
                                         __half* __restrict__ hout,
                                         int m0, int H0, int w, int lane) {
    const int r0 = m0 + w * 16 + (lane >> 2);
    #pragma unroll
    for (int rp = 0; rp < 2; rp++) {
        const int row = r0 + rp * 8;
        #pragma unroll
        for (int j = 0; j < 2; j++) {
            const int colb = H0 + j * 8 + 2 * (lane & 3);
            float2 c2 = *(float2*)(cbuf + (size_t)row * HID + colb);
            float hv[2];
            #pragma unroll
            for (int b = 0; b < 2; b++) {
                const int rg = rp * 2 + b;
                float gi = acc[0 + j][rg] + br[0][j][b];
                float gf = acc[2 + j][rg] + br[1][j][b];
                float gg = acc[4 + j][rg] + br[2][j][b];
                float go = acc[6 + j][rg] + br[3][j][b];
                float c  = b ? c2.y : c2.x;
                float cn = sigm(gf) * c + sigm(gi) * tanhf(gg);
                if (b) c2.y = cn; else c2.x = cn;
                hv[b] = sigm(go) * tanhf(cn);
            }
            *(float2*)(cbuf + (size_t)row * HID + colb) = c2;
            *(__half2*)(hout + (size_t)row * HID + colb) =
                __floats2half2_rn(hv[0], hv[1]);
        }
    }
}

// ----------------------------- output projection -----------------------------
__device__ __forceinline__ void out_calc(int tp, const __half* __restrict__ h2cur,
                                         const float* __restrict__ Wlin,
                                         const float* __restrict__ blin,
                                         float* __restrict__ out, int ct) {
    const int tid = threadIdx.x, lane = tid & 31, wid = tid >> 5;
    if (wid >= 4) return;
    const int b = ct * 4 + wid;                     // within this CTA's M-group
    const __half* hrow = h2cur + (size_t)b * HID;
    float s0 = 0.f, s1 = 0.f;
    #pragma unroll 8
    for (int k = lane; k < HID; k += 32) {
        float hv = __half2float(__ldcg(hrow + k));  // bypass L1 (cross-CTA writer)
        s0 += hv * __ldg(Wlin + k);
        s1 += hv * __ldg(Wlin + HID + k);
    }
    #pragma unroll
    for (int o = 16; o; o >>= 1) {
        s0 += __shfl_xor_sync(0xffffffffu, s0, o);
        s1 += __shfl_xor_sync(0xffffffffu, s1, o);
    }
    if (lane == 0) {
        out[(size_t)b * (T_STEPS * TAGS) + tp * TAGS + 0] = s0 + blin[0];
        out[(size_t)b * (T_STEPS * TAGS) + tp * TAGS + 1] = s1 + blin[1];
    }
}

// ------------------------------ persistent kernel ----------------------------
__global__ void __launch_bounds__(NTHREADS, 1)
lstm_persistent(const float* __restrict__ Wlin, const float* __restrict__ blin,
                float* __restrict__ out) {
    extern __shared__ char smc[];
    const uint32_t smu = (uint32_t)__cvta_generic_to_shared(smc);
    const int tid = threadIdx.x, w = tid >> 5, lane = tid & 31;
    const int ct = blockIdx.x;
    const int mt = ct >> 5, nt = ct & 31;    // 4 M-groups x 32 N-tiles
    const int m0 = mt * MT, n0 = nt * NT, H0 = nt * 16;

    // ---- preload resident W2 slice [64 x 1024] into smem (16 chunk blocks) ----
    {
        const __half* src = g_Wp2h + (size_t)n0 * K2;
        int row = tid >> 2, part = tid & 3;
        for (int ck = 0; ck < 16; ck++) {
            const __half* s = src + (size_t)row * K2 + ck * KC + part * 16;
            uint32_t rb = (uint32_t)(row * 128 + part * 32);
            #pragma unroll
            for (int j = 0; j < 2; j++) {
                uint32_t off = rb + j * 16;
                off ^= (off >> 3) & 0x70u;
                cp16(smu + SM_W2 + ck * 8192 + off, s + j * 8);
            }
        }
        CPA_COMMIT();
        CPA_WAIT0();
        __syncthreads();
    }

    // ---- preload per-thread biases into registers ----
    float b1r[4][2][2], b2r[4][2][2];
    #pragma unroll
    for (int g = 0; g < 4; g++)
        #pragma unroll
        for (int j = 0; j < 2; j++)
            #pragma unroll
            for (int b = 0; b < 2; b++) {
                int c = n0 + g * 16 + j * 8 + 2 * (lane & 3) + b;
                b1r[g][j][b] = g_b1[c];
                b2r[g][j][b] = g_b2[c];
            }

    unsigned round = 0;
    float acc[8][4];

    for (int t = 0; t < T_STEPS; t++) {
        const int rb = t & 1, wb = rb ^ 1;
        if (t > 0) out_calc(t - 1, g_h2[rb], Wlin, blin, out, ct);

        // ---- phase A: gates1 = [x_t, h1] @ W1p^T  (10 chunks, W streamed) ----
        {
            Src sa;
            sa.a0 = g_sigh + ((size_t)t * BATCH + m0) * FEAT; sa.lda0 = FEAT;
            sa.split = FEAT / KC;                             // 2
            sa.a1 = g_h1[rb] + (size_t)m0 * HID;              sa.lda1 = HID;
            sa.W  = g_Wp1h + (size_t)n0 * K1;                 sa.ldw  = K1;
            run_phase(sa, K1 / KC, smu, tid, w, lane, true, acc);
        }
        epilogue(acc, b1r, g_c1, g_h1[wb], m0, H0, w, lane);
        group_sync(mt, ++round);

        // ---- phase B: gates2 = [h1', h2] @ W2p^T  (16 chunks, W resident) ----
        {
            Src sb;
            sb.a0 = g_h1[wb] + (size_t)m0 * HID; sb.lda0 = HID; sb.split = HID / KC;
            sb.a1 = g_h2[rb] + (size_t)m0 * HID; sb.lda1 = HID;
            sb.W  = nullptr;                     sb.ldw  = 0;
            run_phase(sb, K2 / KC, smu, tid, w, lane, false, acc);
        }
        epilogue(acc, b2r, g_c2, g_h2[wb], m0, H0, w, lane);
        group_sync(mt, ++round);
    }
    out_calc(T_STEPS - 1, g_h2[T_STEPS & 1], Wlin, blin, out, ct);
}

// --------------------------------- launcher ----------------------------------
extern "C" void kernel_launch(void* const* d_in, const int* in_sizes, int n_in,
                              void* d_out, int out_size) {
    const float* signal = (const float*)d_in[0];
    const float* Wih1   = (const float*)d_in[1];
    const float* Whh1   = (const float*)d_in[2];
    const float* bih1   = (const float*)d_in[3];
    const float* bhh1   = (const float*)d_in[4];
    const float* Wih2   = (const float*)d_in[5];
    const float* Whh2   = (const float*)d_in[6];
    const float* bih2   = (const float*)d_in[7];
    const float* bhh2   = (const float*)d_in[8];
    const float* Wlin   = (const float*)d_in[9];
    const float* blin   = (const float*)d_in[10];
    float* out = (float*)d_out;

    (void)in_sizes; (void)n_in; (void)out_size;

    cudaFuncSetAttribute(lstm_persistent,
                         cudaFuncAttributeMaxDynamicSharedMemorySize, SMEM_BYTES);

    prep_kernel<<<4096, 256>>>(signal, Wih1, Whh1, bih1, bhh1,
                               Wih2, Whh2, bih2, bhh2);
    lstm_persistent<<<NCTA, NTHREADS, SMEM_BYTES>>>(Wlin, blin, out);
}